// round 12
// baseline (speedup 1.0000x reference)
#include <cuda_runtime.h>
#include <math.h>

#define BB   256
#define DD   256
#define HH   512
#define EE   64
#define NLF  1024
#define KOUT 10

// ---------------- scratch (device globals; no allocation allowed) ----------
__device__ float g_Y1[BB * HH];
__device__ float g_Y2[BB * HH];
__device__ float g_h1[BB * HH];
__device__ float g_h2[BB * HH];
__device__ int   g_bidx[BB];
__device__ float g_rootlp[BB];
__device__ int   g_count[EE];
__device__ int   g_slot[EE * BB];
__device__ float g_rp[4 * BB * EE];     // root-head k-split partials
// expert k-split partial sums (deterministic; no float atomics)
__device__ float g_p1[8 * BB * HH];     // 4 MB
__device__ float g_p2[8 * BB * HH];     // 4 MB
__device__ float g_p3[16 * BB * NLF];   // 16 MB

// ---------------- orderable packing helpers ---------------------------------
__device__ __forceinline__ unsigned int fkey(float v)
{
    unsigned int b = __float_as_uint(v);
    return (b & 0x80000000u) ? ~b : (b | 0x80000000u);
}
__device__ __forceinline__ float funkey(unsigned int b)
{
    return __uint_as_float((b & 0x80000000u) ? (b & 0x7FFFFFFFu) : ~b);
}

// ---------------- root dense layers: 8 samples/block, 2-way k-split ---------
template <int KDIM, int SRCSEL, int DSTSEL, bool ZERO>
__global__ __launch_bounds__(512) void k_rootlin(
    const float* __restrict__ Xin, const float* __restrict__ W,
    const float* __restrict__ bias)
{
    const float* X = (SRCSEL == 0) ? Xin : g_Y1;
    float* Y = (DSTSEL == 0) ? g_Y1 : g_Y2;
    constexpr int KH = KDIM / 2;

    if (ZERO && blockIdx.x == 0 && blockIdx.y == 0 && threadIdx.x < EE)
        g_count[threadIdx.x] = 0;

    __shared__ float4 sX[8][KDIM / 4];
    __shared__ float  sred[8][64];

    int s0 = blockIdx.x * 8;
    int tx = threadIdx.x & 63;
    int sg = (threadIdx.x >> 6) & 3;
    int kg = threadIdx.x >> 8;
    int o  = blockIdx.y * 64 + tx;

    for (int i = threadIdx.x; i < 8 * (KDIM / 4); i += 512) {
        int s = i / (KDIM / 4), kk = i % (KDIM / 4);
        sX[s][kk] = reinterpret_cast<const float4*>(X + (size_t)(s0 + s) * KDIM)[kk];
    }
    __syncthreads();

    const float* Wp = W + (size_t)kg * KH * HH + o;
    float a0 = 0.f, a1 = 0.f;
    int sa = sg * 2, sb = sg * 2 + 1;
#pragma unroll 8
    for (int k4 = 0; k4 < KH / 4; k4++) {
        float w0 = Wp[(size_t)(k4 * 4 + 0) * HH];
        float w1 = Wp[(size_t)(k4 * 4 + 1) * HH];
        float w2 = Wp[(size_t)(k4 * 4 + 2) * HH];
        float w3 = Wp[(size_t)(k4 * 4 + 3) * HH];
        float4 x0 = sX[sa][kg * (KH / 4) + k4];
        float4 x1 = sX[sb][kg * (KH / 4) + k4];
        a0 = fmaf(w0, x0.x, a0); a0 = fmaf(w1, x0.y, a0);
        a0 = fmaf(w2, x0.z, a0); a0 = fmaf(w3, x0.w, a0);
        a1 = fmaf(w0, x1.x, a1); a1 = fmaf(w1, x1.y, a1);
        a1 = fmaf(w2, x1.z, a1); a1 = fmaf(w3, x1.w, a1);
    }
    if (kg == 1) { sred[sa][tx] = a0; sred[sb][tx] = a1; }
    __syncthreads();
    if (kg == 0) {
        float bb = bias[o];
        Y[(size_t)(s0 + sa) * HH + o] = fmaxf(a0 + sred[sa][tx] + bb, 0.f);
        Y[(size_t)(s0 + sb) * HH + o] = fmaxf(a1 + sred[sb][tx] + bb, 0.f);
    }
}

// ---------------- root head GEMM: k-split partials ---------------------------
__global__ __launch_bounds__(512) void k_rootgemm(const float* __restrict__ W)
{
    constexpr int KH = HH / 4;
    __shared__ float4 sX[16][KH / 4];   // 8 KB

    int s0 = blockIdx.x * 16;
    int kq = blockIdx.y;
    int e  = threadIdx.x & 63;
    int sj = threadIdx.x >> 6;

    for (int i = threadIdx.x; i < 16 * (KH / 4); i += 512) {
        int s = i / (KH / 4), kk = i % (KH / 4);
        sX[s][kk] = reinterpret_cast<const float4*>(
            g_Y2 + (size_t)(s0 + s) * HH + kq * KH)[kk];
    }
    __syncthreads();

    const float* Wp = W + (size_t)kq * KH * EE + e;
    float a0 = 0.f, a1 = 0.f;
    int sa = sj * 2, sb = sj * 2 + 1;
#pragma unroll 8
    for (int k4 = 0; k4 < KH / 4; k4++) {
        float w0 = Wp[(size_t)(k4 * 4 + 0) * EE];
        float w1 = Wp[(size_t)(k4 * 4 + 1) * EE];
        float w2 = Wp[(size_t)(k4 * 4 + 2) * EE];
        float w3 = Wp[(size_t)(k4 * 4 + 3) * EE];
        float4 x0 = sX[sa][k4];
        float4 x1 = sX[sb][k4];
        a0 = fmaf(w0, x0.x, a0); a0 = fmaf(w1, x0.y, a0);
        a0 = fmaf(w2, x0.z, a0); a0 = fmaf(w3, x0.w, a0);
        a1 = fmaf(w0, x1.x, a1); a1 = fmaf(w1, x1.y, a1);
        a1 = fmaf(w2, x1.z, a1); a1 = fmaf(w3, x1.w, a1);
    }
    g_rp[(size_t)kq * BB * EE + (size_t)(s0 + sa) * EE + e] = a0;
    g_rp[(size_t)kq * BB * EE + (size_t)(s0 + sb) * EE + e] = a1;
}

// ---------------- root routing: warp per sample, grid 32 ---------------------
__global__ __launch_bounds__(256) void k_route(const float* __restrict__ bias)
{
    int w = threadIdx.x >> 5;
    int l = threadIdx.x & 31;
    int b = blockIdx.x * 8 + w;

    int e0 = l, e1 = l + 32;
    float p00 = g_rp[(size_t)0 * BB * EE + (size_t)b * EE + e0];
    float p01 = g_rp[(size_t)1 * BB * EE + (size_t)b * EE + e0];
    float p02 = g_rp[(size_t)2 * BB * EE + (size_t)b * EE + e0];
    float p03 = g_rp[(size_t)3 * BB * EE + (size_t)b * EE + e0];
    float p10 = g_rp[(size_t)0 * BB * EE + (size_t)b * EE + e1];
    float p11 = g_rp[(size_t)1 * BB * EE + (size_t)b * EE + e1];
    float p12 = g_rp[(size_t)2 * BB * EE + (size_t)b * EE + e1];
    float p13 = g_rp[(size_t)3 * BB * EE + (size_t)b * EE + e1];
    float v0 = bias[e0] + (p00 + p01) + (p02 + p03);
    float v1 = bias[e1] + (p10 + p11) + (p12 + p13);

    unsigned long long k0 = ((unsigned long long)fkey(v0) << 32) | (unsigned int)(EE - 1 - e0);
    unsigned long long k1 = ((unsigned long long)fkey(v1) << 32) | (unsigned int)(EE - 1 - e1);
    unsigned long long best = max(k0, k1);
#pragma unroll
    for (int off = 16; off > 0; off >>= 1) {
        unsigned long long o2 = __shfl_down_sync(0xFFFFFFFFu, best, off);
        best = max(best, o2);
    }
    best = __shfl_sync(0xFFFFFFFFu, best, 0);
    float mx = funkey((unsigned int)(best >> 32));
    int   mi = EE - 1 - (int)(best & 0xFFFFFFFFu);

    float se = __expf(v0 - mx) + __expf(v1 - mx);
#pragma unroll
    for (int off = 16; off > 0; off >>= 1)
        se += __shfl_down_sync(0xFFFFFFFFu, se, off);

    if (l == 0) {
        g_bidx[b]   = mi;
        g_rootlp[b] = -__logf(se);       // lp at argmax = -log(sum exp(v-mx))
        int pos = atomicAdd(&g_count[mi], 1);
        g_slot[mi * BB + pos] = b;
    }
}

// ---------------- expert fma helper -----------------------------------------
__device__ __forceinline__ void fma4(float4& a, const float4 w, const float s)
{
    a.x = fmaf(w.x, s, a.x); a.y = fmaf(w.y, s, a.y);
    a.z = fmaf(w.z, s, a.z); a.w = fmaf(w.w, s, a.w);
}

// ---------------- grouped expert dense layer, balanced z tiles ---------------
// grid (EE, KS, NZ); 256 thr. Tile = 4 samples; block z handles tiles z, z+NZ...
// For OT=512 the 2 in-block k-subgroups write different partial slices.
template <int KDIM, int KS, int OT, int SRC, int DST, int NZ>
__global__ __launch_bounds__(256) void k_exp(
    const float* __restrict__ Xin, const float* __restrict__ Wsrc)
{
    constexpr int OTH  = OT / 4;        // 128 or 256
    constexpr int KSUB = 256 / OTH;     // 2 or 1
    constexpr int KR   = KDIM / KS;
    constexpr int KT   = KR / KSUB;

    const float* X = (SRC == 0) ? Xin : ((SRC == 1) ? g_h1 : g_h2);
    float* Pbase = (DST == 0) ? g_p1 : ((DST == 1) ? g_p2 : g_p3);

    int ex = blockIdx.x, ks = blockIdx.y, z = blockIdx.z;
    int c = g_count[ex];
    if (z * 4 >= c) return;

    int ot = threadIdx.x % OTH;
    int kg = threadIdx.x / OTH;
    int o  = ot * 4;
    int sxoff = kg * (KT / 4);

    const float* W = Wsrc + (size_t)ex * KDIM * OT + (size_t)(ks * KR + kg * KT) * OT;
    float* P = Pbase + (size_t)(ks * KSUB + kg) * BB * OT;

    __shared__ float4 sX[4][KR / 4];
    __shared__ int    sB[4];

    for (int st = z * 4; st < c; st += NZ * 4) {
        int ct = min(4, c - st);
        __syncthreads();
        if (threadIdx.x < 4)
            sB[threadIdx.x] = g_slot[ex * BB + st + ((threadIdx.x < ct) ? threadIdx.x : 0)];
        __syncthreads();
        for (int i = threadIdx.x; i < 4 * (KR / 4); i += 256) {
            int s = i / (KR / 4), kk = i % (KR / 4);
            sX[s][kk] = *reinterpret_cast<const float4*>(
                X + (size_t)sB[s] * KDIM + ks * KR + kk * 4);
        }
        __syncthreads();

        float4 acc[4];
#pragma unroll
        for (int j = 0; j < 4; j++) acc[j] = make_float4(0.f, 0.f, 0.f, 0.f);

#pragma unroll 8
        for (int k4 = 0; k4 < KT / 4; k4++) {
            const float* wp = W + (size_t)(k4 * 4) * OT + o;
            float4 w0 = *reinterpret_cast<const float4*>(wp);
            float4 w1 = *reinterpret_cast<const float4*>(wp + OT);
            float4 w2 = *reinterpret_cast<const float4*>(wp + 2 * OT);
            float4 w3 = *reinterpret_cast<const float4*>(wp + 3 * OT);
#pragma unroll
            for (int j = 0; j < 4; j++) {
                float4 x = sX[j][sxoff + k4];
                fma4(acc[j], w0, x.x);
                fma4(acc[j], w1, x.y);
                fma4(acc[j], w2, x.z);
                fma4(acc[j], w3, x.w);
            }
        }
#pragma unroll
        for (int j = 0; j < 4; j++)
            if (j < ct)
                *reinterpret_cast<float4*>(P + (size_t)sB[j] * OT + o) = acc[j];
    }
}

// ---------------- reduce 8 partials + bias + relu ----------------------------
template <int OT, int DST>
__global__ __launch_bounds__(256) void k_red(const float* __restrict__ ebias)
{
    const float* Pb = (DST == 0) ? g_p1 : g_p2;
    float* Y = (DST == 0) ? g_h1 : g_h2;
    int idx = blockIdx.x * 256 + threadIdx.x;          // float4 index
    const int row4 = OT / 4;
    int b = idx / row4, o4 = idx % row4;
    int o = o4 * 4;

    float4 s = *reinterpret_cast<const float4*>(Pb + (size_t)b * OT + o);
#pragma unroll
    for (int p = 1; p < 8; p++) {
        float4 v = *reinterpret_cast<const float4*>(Pb + ((size_t)p * BB + b) * OT + o);
        s.x += v.x; s.y += v.y; s.z += v.z; s.w += v.w;
    }
    float4 bb = *reinterpret_cast<const float4*>(ebias + (size_t)g_bidx[b] * OT + o);
    s.x = fmaxf(s.x + bb.x, 0.f);
    s.y = fmaxf(s.y + bb.y, 0.f);
    s.z = fmaxf(s.z + bb.z, 0.f);
    s.w = fmaxf(s.w + bb.w, 0.f);
    *reinterpret_cast<float4*>(Y + (size_t)b * OT + o) = s;
}

// ---------------- final: L3 reduce(16) + log_softmax + top-11 + emit --------
__global__ __launch_bounds__(256) void k_final(
    float* __restrict__ out, const float* __restrict__ eb3)
{
    int b = blockIdx.x;
    __shared__ float sv[NLF];
    __shared__ float orig[NLF];
    __shared__ unsigned long long swarp[8];
    __shared__ float sred[8];
    __shared__ float smx, slse;
    __shared__ int   chosen[KOUT + 1];

    int branch = g_bidx[b];
    int wid = threadIdx.x >> 5;
    int lane = threadIdx.x & 31;

    for (int i = threadIdx.x; i < NLF; i += 256) {
        float v = eb3[(size_t)branch * NLF + i];
#pragma unroll
        for (int p = 0; p < 16; p++)
            v += g_p3[((size_t)p * BB + b) * NLF + i];
        sv[i] = v;
        orig[i] = v;
    }
    __syncthreads();

    for (int t = 0; t < KOUT + 1; t++) {
        unsigned long long best = 0ULL;
        for (int i = threadIdx.x; i < NLF; i += 256)
            best = max(best, ((unsigned long long)fkey(sv[i]) << 32) |
                             (unsigned int)(NLF - 1 - i));
#pragma unroll
        for (int off = 16; off > 0; off >>= 1) {
            unsigned long long o2 = __shfl_down_sync(0xFFFFFFFFu, best, off);
            best = max(best, o2);
        }
        if (lane == 0) swarp[wid] = best;
        __syncthreads();
        if (threadIdx.x == 0) {
            unsigned long long bb = swarp[0];
#pragma unroll
            for (int i2 = 1; i2 < 8; i2++) bb = max(bb, swarp[i2]);
            int idx = NLF - 1 - (int)(bb & 0xFFFFFFFFu);
            chosen[t] = idx;
            sv[idx] = -INFINITY;
            if (t == 0) smx = funkey((unsigned int)(bb >> 32));
        }
        __syncthreads();

        if (t == 0) {
            float mx = smx;
            float ls = 0.f;
            for (int i = threadIdx.x; i < NLF; i += 256)
                ls += __expf(orig[i] - mx);
#pragma unroll
            for (int off = 16; off > 0; off >>= 1)
                ls += __shfl_down_sync(0xFFFFFFFFu, ls, off);
            if (lane == 0) sred[wid] = ls;
            __syncthreads();
            if (threadIdx.x == 0) {
                float tot = 0.f;
#pragma unroll
                for (int i2 = 0; i2 < 8; i2++) tot += sred[i2];
                slse = mx + __logf(tot);
            }
            __syncthreads();
        }
    }

    if (threadIdx.x == 0) {
        float rlp   = g_rootlp[b];
        float lse   = slse;
        float* traj = out;                    // [B][K][2] as float
        float* flp  = out + BB * KOUT * 2;    // [B][K]
        int w = 0;
        for (int t = 0; t < KOUT + 1 && w < KOUT; t++) {
            int item = chosen[t];
            if (item == 0 && branch == 0) continue;   // drop id-0 trajectory
            traj[((size_t)b * KOUT + w) * 2 + 0] = (float)branch;
            traj[((size_t)b * KOUT + w) * 2 + 1] = (float)item;
            flp[(size_t)b * KOUT + w] = (orig[item] - lse) + rlp;
            w++;
        }
    }
}

// ---------------- launch ----------------------------------------------------
extern "C" void kernel_launch(void* const* d_in, const int* in_sizes, int n_in,
                              void* d_out, int out_size)
{
    const float* state = (const float*)d_in[0];
    const float* rW1   = (const float*)d_in[1];
    const float* rb1   = (const float*)d_in[2];
    const float* rW2   = (const float*)d_in[3];
    const float* rb2   = (const float*)d_in[4];
    const float* rW3   = (const float*)d_in[5];
    const float* rb3   = (const float*)d_in[6];
    const float* eW1   = (const float*)d_in[7];
    const float* eb1   = (const float*)d_in[8];
    const float* eW2   = (const float*)d_in[9];
    const float* eb2   = (const float*)d_in[10];
    const float* eW3   = (const float*)d_in[11];
    const float* eb3   = (const float*)d_in[12];
    float* out = (float*)d_out;

    k_rootlin<DD, 0, 0, true ><<<dim3(BB / 8, HH / 64), 512>>>(state, rW1, rb1);
    k_rootlin<HH, 1, 1, false><<<dim3(BB / 8, HH / 64), 512>>>(nullptr, rW2, rb2);
    k_rootgemm<<<dim3(BB / 16, 4), 512>>>(rW3);
    k_route<<<BB / 8, 256>>>(rb3);

    k_exp<DD, 4,  HH,  0, 0, 4><<<dim3(EE, 4,  4), 256>>>(state,  eW1);
    k_red<HH, 0><<<(BB * HH / 4) / 256, 256>>>(eb1);
    k_exp<HH, 4,  HH,  1, 1, 4><<<dim3(EE, 4,  4), 256>>>(nullptr, eW2);
    k_red<HH, 1><<<(BB * HH / 4) / 256, 256>>>(eb2);
    k_exp<HH, 16, NLF, 2, 2, 2><<<dim3(EE, 16, 2), 256>>>(nullptr, eW3);  // KT=32
    k_final<<<BB, 256>>>(out, eb3);
}

// round 13
// speedup vs baseline: 1.0230x; 1.0230x over previous
#include <cuda_runtime.h>
#include <math.h>

#define BB   256
#define DD   256
#define HH   512
#define EE   64
#define NLF  1024
#define KOUT 10

// ---------------- scratch (device globals; no allocation allowed) ----------
__device__ float g_Y1[BB * HH];
__device__ float g_Y2[BB * HH];
__device__ float g_h1[BB * HH];
__device__ float g_h2[BB * HH];
__device__ int   g_bidx[BB];
__device__ float g_rootlp[BB];
__device__ int   g_count[EE];
__device__ int   g_slot[EE * BB];
__device__ float g_rp[4 * BB * EE];     // root-head k-split partials
// expert k-split partial sums (deterministic; no float atomics)
__device__ float g_p1[8 * BB * HH];     // 4 MB
__device__ float g_p2[8 * BB * HH];     // 4 MB
__device__ float g_p3[8 * BB * NLF];    // 8 MB

// ---------------- orderable packing helpers ---------------------------------
__device__ __forceinline__ unsigned int fkey(float v)
{
    unsigned int b = __float_as_uint(v);
    return (b & 0x80000000u) ? ~b : (b | 0x80000000u);
}
__device__ __forceinline__ float funkey(unsigned int b)
{
    return __uint_as_float((b & 0x80000000u) ? (b & 0x7FFFFFFFu) : ~b);
}

// ---------------- root dense layers: 8 samples/block, 2-way k-split ---------
template <int KDIM, int SRCSEL, int DSTSEL, bool ZERO>
__global__ __launch_bounds__(512) void k_rootlin(
    const float* __restrict__ Xin, const float* __restrict__ W,
    const float* __restrict__ bias)
{
    const float* X = (SRCSEL == 0) ? Xin : g_Y1;
    float* Y = (DSTSEL == 0) ? g_Y1 : g_Y2;
    constexpr int KH = KDIM / 2;

    if (ZERO && blockIdx.x == 0 && blockIdx.y == 0 && threadIdx.x < EE)
        g_count[threadIdx.x] = 0;

    __shared__ float4 sX[8][KDIM / 4];
    __shared__ float  sred[8][64];

    int s0 = blockIdx.x * 8;
    int tx = threadIdx.x & 63;
    int sg = (threadIdx.x >> 6) & 3;
    int kg = threadIdx.x >> 8;
    int o  = blockIdx.y * 64 + tx;

    for (int i = threadIdx.x; i < 8 * (KDIM / 4); i += 512) {
        int s = i / (KDIM / 4), kk = i % (KDIM / 4);
        sX[s][kk] = reinterpret_cast<const float4*>(X + (size_t)(s0 + s) * KDIM)[kk];
    }
    __syncthreads();

    const float* Wp = W + (size_t)kg * KH * HH + o;
    float a0 = 0.f, a1 = 0.f;
    int sa = sg * 2, sb = sg * 2 + 1;
#pragma unroll 8
    for (int k4 = 0; k4 < KH / 4; k4++) {
        float w0 = Wp[(size_t)(k4 * 4 + 0) * HH];
        float w1 = Wp[(size_t)(k4 * 4 + 1) * HH];
        float w2 = Wp[(size_t)(k4 * 4 + 2) * HH];
        float w3 = Wp[(size_t)(k4 * 4 + 3) * HH];
        float4 x0 = sX[sa][kg * (KH / 4) + k4];
        float4 x1 = sX[sb][kg * (KH / 4) + k4];
        a0 = fmaf(w0, x0.x, a0); a0 = fmaf(w1, x0.y, a0);
        a0 = fmaf(w2, x0.z, a0); a0 = fmaf(w3, x0.w, a0);
        a1 = fmaf(w0, x1.x, a1); a1 = fmaf(w1, x1.y, a1);
        a1 = fmaf(w2, x1.z, a1); a1 = fmaf(w3, x1.w, a1);
    }
    if (kg == 1) { sred[sa][tx] = a0; sred[sb][tx] = a1; }
    __syncthreads();
    if (kg == 0) {
        float bb = bias[o];
        Y[(size_t)(s0 + sa) * HH + o] = fmaxf(a0 + sred[sa][tx] + bb, 0.f);
        Y[(size_t)(s0 + sb) * HH + o] = fmaxf(a1 + sred[sb][tx] + bb, 0.f);
    }
}

// ---------------- root head GEMM: k-split partials ---------------------------
__global__ __launch_bounds__(512) void k_rootgemm(const float* __restrict__ W)
{
    constexpr int KH = HH / 4;
    __shared__ float4 sX[16][KH / 4];   // 8 KB

    int s0 = blockIdx.x * 16;
    int kq = blockIdx.y;
    int e  = threadIdx.x & 63;
    int sj = threadIdx.x >> 6;

    for (int i = threadIdx.x; i < 16 * (KH / 4); i += 512) {
        int s = i / (KH / 4), kk = i % (KH / 4);
        sX[s][kk] = reinterpret_cast<const float4*>(
            g_Y2 + (size_t)(s0 + s) * HH + kq * KH)[kk];
    }
    __syncthreads();

    const float* Wp = W + (size_t)kq * KH * EE + e;
    float a0 = 0.f, a1 = 0.f;
    int sa = sj * 2, sb = sj * 2 + 1;
#pragma unroll 8
    for (int k4 = 0; k4 < KH / 4; k4++) {
        float w0 = Wp[(size_t)(k4 * 4 + 0) * EE];
        float w1 = Wp[(size_t)(k4 * 4 + 1) * EE];
        float w2 = Wp[(size_t)(k4 * 4 + 2) * EE];
        float w3 = Wp[(size_t)(k4 * 4 + 3) * EE];
        float4 x0 = sX[sa][k4];
        float4 x1 = sX[sb][k4];
        a0 = fmaf(w0, x0.x, a0); a0 = fmaf(w1, x0.y, a0);
        a0 = fmaf(w2, x0.z, a0); a0 = fmaf(w3, x0.w, a0);
        a1 = fmaf(w0, x1.x, a1); a1 = fmaf(w1, x1.y, a1);
        a1 = fmaf(w2, x1.z, a1); a1 = fmaf(w3, x1.w, a1);
    }
    g_rp[(size_t)kq * BB * EE + (size_t)(s0 + sa) * EE + e] = a0;
    g_rp[(size_t)kq * BB * EE + (size_t)(s0 + sb) * EE + e] = a1;
}

// ---------------- root routing: warp per sample, grid 32 ---------------------
__global__ __launch_bounds__(256) void k_route(const float* __restrict__ bias)
{
    int w = threadIdx.x >> 5;
    int l = threadIdx.x & 31;
    int b = blockIdx.x * 8 + w;

    int e0 = l, e1 = l + 32;
    float p00 = g_rp[(size_t)0 * BB * EE + (size_t)b * EE + e0];
    float p01 = g_rp[(size_t)1 * BB * EE + (size_t)b * EE + e0];
    float p02 = g_rp[(size_t)2 * BB * EE + (size_t)b * EE + e0];
    float p03 = g_rp[(size_t)3 * BB * EE + (size_t)b * EE + e0];
    float p10 = g_rp[(size_t)0 * BB * EE + (size_t)b * EE + e1];
    float p11 = g_rp[(size_t)1 * BB * EE + (size_t)b * EE + e1];
    float p12 = g_rp[(size_t)2 * BB * EE + (size_t)b * EE + e1];
    float p13 = g_rp[(size_t)3 * BB * EE + (size_t)b * EE + e1];
    float v0 = bias[e0] + (p00 + p01) + (p02 + p03);
    float v1 = bias[e1] + (p10 + p11) + (p12 + p13);

    unsigned long long k0 = ((unsigned long long)fkey(v0) << 32) | (unsigned int)(EE - 1 - e0);
    unsigned long long k1 = ((unsigned long long)fkey(v1) << 32) | (unsigned int)(EE - 1 - e1);
    unsigned long long best = max(k0, k1);
#pragma unroll
    for (int off = 16; off > 0; off >>= 1) {
        unsigned long long o2 = __shfl_down_sync(0xFFFFFFFFu, best, off);
        best = max(best, o2);
    }
    best = __shfl_sync(0xFFFFFFFFu, best, 0);
    float mx = funkey((unsigned int)(best >> 32));
    int   mi = EE - 1 - (int)(best & 0xFFFFFFFFu);

    float se = __expf(v0 - mx) + __expf(v1 - mx);
#pragma unroll
    for (int off = 16; off > 0; off >>= 1)
        se += __shfl_down_sync(0xFFFFFFFFu, se, off);

    if (l == 0) {
        g_bidx[b]   = mi;
        g_rootlp[b] = -__logf(se);       // lp at argmax = -log(sum exp(v-mx))
        int pos = atomicAdd(&g_count[mi], 1);
        g_slot[mi * BB + pos] = b;
    }
}

// ---------------- expert fma helper -----------------------------------------
__device__ __forceinline__ void fma4(float4& a, const float4 w, const float s)
{
    a.x = fmaf(w.x, s, a.x); a.y = fmaf(w.y, s, a.y);
    a.z = fmaf(w.z, s, a.z); a.w = fmaf(w.w, s, a.w);
}

// ---------------- grouped expert dense layer, balanced z tiles ---------------
// grid (EE, KS, NZ); 256 thr. Tile = 4 samples; block z handles tiles z, z+NZ...
// For OT=512 the 2 in-block k-subgroups write different partial slices.
template <int KDIM, int KS, int OT, int SRC, int DST, int NZ>
__global__ __launch_bounds__(256) void k_exp(
    const float* __restrict__ Xin, const float* __restrict__ Wsrc)
{
    constexpr int OTH  = OT / 4;        // 128 or 256
    constexpr int KSUB = 256 / OTH;     // 2 or 1
    constexpr int KR   = KDIM / KS;
    constexpr int KT   = KR / KSUB;

    const float* X = (SRC == 0) ? Xin : ((SRC == 1) ? g_h1 : g_h2);
    float* Pbase = (DST == 0) ? g_p1 : ((DST == 1) ? g_p2 : g_p3);

    int ex = blockIdx.x, ks = blockIdx.y, z = blockIdx.z;
    int c = g_count[ex];
    if (z * 4 >= c) return;

    int ot = threadIdx.x % OTH;
    int kg = threadIdx.x / OTH;
    int o  = ot * 4;
    int sxoff = kg * (KT / 4);

    const float* W = Wsrc + (size_t)ex * KDIM * OT + (size_t)(ks * KR + kg * KT) * OT;
    float* P = Pbase + (size_t)(ks * KSUB + kg) * BB * OT;

    __shared__ float4 sX[4][KR / 4];
    __shared__ int    sB[4];

    for (int st = z * 4; st < c; st += NZ * 4) {
        int ct = min(4, c - st);
        __syncthreads();
        if (threadIdx.x < 4)
            sB[threadIdx.x] = g_slot[ex * BB + st + ((threadIdx.x < ct) ? threadIdx.x : 0)];
        __syncthreads();
        for (int i = threadIdx.x; i < 4 * (KR / 4); i += 256) {
            int s = i / (KR / 4), kk = i % (KR / 4);
            sX[s][kk] = *reinterpret_cast<const float4*>(
                X + (size_t)sB[s] * KDIM + ks * KR + kk * 4);
        }
        __syncthreads();

        float4 acc[4];
#pragma unroll
        for (int j = 0; j < 4; j++) acc[j] = make_float4(0.f, 0.f, 0.f, 0.f);

#pragma unroll 8
        for (int k4 = 0; k4 < KT / 4; k4++) {
            const float* wp = W + (size_t)(k4 * 4) * OT + o;
            float4 w0 = *reinterpret_cast<const float4*>(wp);
            float4 w1 = *reinterpret_cast<const float4*>(wp + OT);
            float4 w2 = *reinterpret_cast<const float4*>(wp + 2 * OT);
            float4 w3 = *reinterpret_cast<const float4*>(wp + 3 * OT);
#pragma unroll
            for (int j = 0; j < 4; j++) {
                float4 x = sX[j][sxoff + k4];
                fma4(acc[j], w0, x.x);
                fma4(acc[j], w1, x.y);
                fma4(acc[j], w2, x.z);
                fma4(acc[j], w3, x.w);
            }
        }
#pragma unroll
        for (int j = 0; j < 4; j++)
            if (j < ct)
                *reinterpret_cast<float4*>(P + (size_t)sB[j] * OT + o) = acc[j];
    }
}

// ---------------- reduce 8 partials + bias + relu ----------------------------
template <int OT, int DST>
__global__ __launch_bounds__(256) void k_red(const float* __restrict__ ebias)
{
    const float* Pb = (DST == 0) ? g_p1 : g_p2;
    float* Y = (DST == 0) ? g_h1 : g_h2;
    int idx = blockIdx.x * 256 + threadIdx.x;          // float4 index
    const int row4 = OT / 4;
    int b = idx / row4, o4 = idx % row4;
    int o = o4 * 4;

    float4 s = *reinterpret_cast<const float4*>(Pb + (size_t)b * OT + o);
#pragma unroll
    for (int p = 1; p < 8; p++) {
        float4 v = *reinterpret_cast<const float4*>(Pb + ((size_t)p * BB + b) * OT + o);
        s.x += v.x; s.y += v.y; s.z += v.z; s.w += v.w;
    }
    float4 bb = *reinterpret_cast<const float4*>(ebias + (size_t)g_bidx[b] * OT + o);
    s.x = fmaxf(s.x + bb.x, 0.f);
    s.y = fmaxf(s.y + bb.y, 0.f);
    s.z = fmaxf(s.z + bb.z, 0.f);
    s.w = fmaxf(s.w + bb.w, 0.f);
    *reinterpret_cast<float4*>(Y + (size_t)b * OT + o) = s;
}

// ---------------- final: L3 reduce(8, float4) + log_softmax + top-11 --------
__global__ __launch_bounds__(256) void k_final(
    float* __restrict__ out, const float* __restrict__ eb3)
{
    int b = blockIdx.x;
    __shared__ __align__(16) float sv[NLF];
    __shared__ __align__(16) float orig[NLF];
    __shared__ unsigned long long swarp[8];
    __shared__ float sred[8];
    __shared__ float smx, slse;
    __shared__ int   chosen[KOUT + 1];

    int branch = g_bidx[b];
    int wid = threadIdx.x >> 5;
    int lane = threadIdx.x & 31;

    // vectorized reduce: thread t owns elements [4t, 4t+4) -> 9 float4 loads
    {
        int i4 = threadIdx.x * 4;
        float4 v = *reinterpret_cast<const float4*>(eb3 + (size_t)branch * NLF + i4);
#pragma unroll
        for (int p = 0; p < 8; p++) {
            float4 u = *reinterpret_cast<const float4*>(
                g_p3 + ((size_t)p * BB + b) * NLF + i4);
            v.x += u.x; v.y += u.y; v.z += u.z; v.w += u.w;
        }
        *reinterpret_cast<float4*>(sv + i4)   = v;
        *reinterpret_cast<float4*>(orig + i4) = v;
    }
    __syncthreads();

    for (int t = 0; t < KOUT + 1; t++) {
        unsigned long long best = 0ULL;
        for (int i = threadIdx.x; i < NLF; i += 256)
            best = max(best, ((unsigned long long)fkey(sv[i]) << 32) |
                             (unsigned int)(NLF - 1 - i));
#pragma unroll
        for (int off = 16; off > 0; off >>= 1) {
            unsigned long long o2 = __shfl_down_sync(0xFFFFFFFFu, best, off);
            best = max(best, o2);
        }
        if (lane == 0) swarp[wid] = best;
        __syncthreads();
        if (threadIdx.x == 0) {
            unsigned long long bb = swarp[0];
#pragma unroll
            for (int i2 = 1; i2 < 8; i2++) bb = max(bb, swarp[i2]);
            int idx = NLF - 1 - (int)(bb & 0xFFFFFFFFu);
            chosen[t] = idx;
            sv[idx] = -INFINITY;
            if (t == 0) smx = funkey((unsigned int)(bb >> 32));
        }
        __syncthreads();

        if (t == 0) {
            float mx = smx;
            float ls = 0.f;
            for (int i = threadIdx.x; i < NLF; i += 256)
                ls += __expf(orig[i] - mx);
#pragma unroll
            for (int off = 16; off > 0; off >>= 1)
                ls += __shfl_down_sync(0xFFFFFFFFu, ls, off);
            if (lane == 0) sred[wid] = ls;
            __syncthreads();
            if (threadIdx.x == 0) {
                float tot = 0.f;
#pragma unroll
                for (int i2 = 0; i2 < 8; i2++) tot += sred[i2];
                slse = mx + __logf(tot);
            }
            __syncthreads();
        }
    }

    if (threadIdx.x == 0) {
        float rlp   = g_rootlp[b];
        float lse   = slse;
        float* traj = out;                    // [B][K][2] as float
        float* flp  = out + BB * KOUT * 2;    // [B][K]
        int w = 0;
        for (int t = 0; t < KOUT + 1 && w < KOUT; t++) {
            int item = chosen[t];
            if (item == 0 && branch == 0) continue;   // drop id-0 trajectory
            traj[((size_t)b * KOUT + w) * 2 + 0] = (float)branch;
            traj[((size_t)b * KOUT + w) * 2 + 1] = (float)item;
            flp[(size_t)b * KOUT + w] = (orig[item] - lse) + rlp;
            w++;
        }
    }
}

// ---------------- launch ----------------------------------------------------
extern "C" void kernel_launch(void* const* d_in, const int* in_sizes, int n_in,
                              void* d_out, int out_size)
{
    const float* state = (const float*)d_in[0];
    const float* rW1   = (const float*)d_in[1];
    const float* rb1   = (const float*)d_in[2];
    const float* rW2   = (const float*)d_in[3];
    const float* rb2   = (const float*)d_in[4];
    const float* rW3   = (const float*)d_in[5];
    const float* rb3   = (const float*)d_in[6];
    const float* eW1   = (const float*)d_in[7];
    const float* eb1   = (const float*)d_in[8];
    const float* eW2   = (const float*)d_in[9];
    const float* eb2   = (const float*)d_in[10];
    const float* eW3   = (const float*)d_in[11];
    const float* eb3   = (const float*)d_in[12];
    float* out = (float*)d_out;

    k_rootlin<DD, 0, 0, true ><<<dim3(BB / 8, HH / 64), 512>>>(state, rW1, rb1);
    k_rootlin<HH, 1, 1, false><<<dim3(BB / 8, HH / 64), 512>>>(nullptr, rW2, rb2);
    k_rootgemm<<<dim3(BB / 16, 4), 512>>>(rW3);
    k_route<<<BB / 8, 256>>>(rb3);

    k_exp<DD, 4, HH,  0, 0, 4><<<dim3(EE, 4, 4), 256>>>(state,  eW1);
    k_red<HH, 0><<<(BB * HH / 4) / 256, 256>>>(eb1);
    k_exp<HH, 4, HH,  1, 1, 4><<<dim3(EE, 4, 4), 256>>>(nullptr, eW2);
    k_red<HH, 1><<<(BB * HH / 4) / 256, 256>>>(eb2);
    k_exp<HH, 8, NLF, 2, 2, 4><<<dim3(EE, 8, 4), 256>>>(nullptr, eW3);
    k_final<<<BB, 256>>>(out, eb3);
}

// round 14
// speedup vs baseline: 1.2618x; 1.2334x over previous
#include <cuda_runtime.h>
#include <math.h>

#define BB   256
#define DD   256
#define HH   512
#define EE   64
#define NLF  1024
#define KOUT 10

// ---------------- scratch (device globals; no allocation allowed) ----------
__device__ float g_Y1[BB * HH];
__device__ float g_Y2[BB * HH];
__device__ float g_h1[BB * HH];
__device__ float g_h2[BB * HH];
__device__ int   g_bidx[BB];
__device__ float g_rootlp[BB];
__device__ int   g_count[EE];
__device__ int   g_slot[EE * BB];
__device__ float g_rp[4 * BB * EE];     // root-head k-split partials
// expert k-split partial sums (deterministic; no float atomics)
__device__ float g_p1[8 * BB * HH];     // 4 MB
__device__ float g_p2[8 * BB * HH];     // 4 MB
__device__ float g_p3[8 * BB * NLF];    // 8 MB

// ---------------- orderable packing helpers ---------------------------------
__device__ __forceinline__ unsigned int fkey(float v)
{
    unsigned int b = __float_as_uint(v);
    return (b & 0x80000000u) ? ~b : (b | 0x80000000u);
}
__device__ __forceinline__ float funkey(unsigned int b)
{
    return __uint_as_float((b & 0x80000000u) ? (b & 0x7FFFFFFFu) : ~b);
}

// ---------------- root dense layers: 4 samples/block, 4-way k-split ---------
// grid (B/4, H/64), 512 thr: o(64) x sg(2, 2 samples each) x kg(4)
template <int KDIM, int SRCSEL, int DSTSEL, bool ZERO>
__global__ __launch_bounds__(512) void k_rootlin(
    const float* __restrict__ Xin, const float* __restrict__ W,
    const float* __restrict__ bias)
{
    const float* X = (SRCSEL == 0) ? Xin : g_Y1;
    float* Y = (DSTSEL == 0) ? g_Y1 : g_Y2;
    constexpr int KH = KDIM / 4;

    if (ZERO && blockIdx.x == 0 && blockIdx.y == 0 && threadIdx.x < EE)
        g_count[threadIdx.x] = 0;

    __shared__ float4 sX[4][KDIM / 4];
    __shared__ float  sred[3][4][64];

    int s0 = blockIdx.x * 4;
    int tx = threadIdx.x & 63;
    int sg = (threadIdx.x >> 6) & 1;
    int kg = threadIdx.x >> 7;            // 0..3
    int o  = blockIdx.y * 64 + tx;

    for (int i = threadIdx.x; i < 4 * (KDIM / 4); i += 512) {
        int s = i / (KDIM / 4), kk = i % (KDIM / 4);
        sX[s][kk] = reinterpret_cast<const float4*>(X + (size_t)(s0 + s) * KDIM)[kk];
    }
    __syncthreads();

    const float* Wp = W + (size_t)kg * KH * HH + o;
    float a0 = 0.f, a1 = 0.f;
    int sa = sg * 2, sb = sg * 2 + 1;
#pragma unroll 8
    for (int k4 = 0; k4 < KH / 4; k4++) {
        float w0 = Wp[(size_t)(k4 * 4 + 0) * HH];
        float w1 = Wp[(size_t)(k4 * 4 + 1) * HH];
        float w2 = Wp[(size_t)(k4 * 4 + 2) * HH];
        float w3 = Wp[(size_t)(k4 * 4 + 3) * HH];
        float4 x0 = sX[sa][kg * (KH / 4) + k4];
        float4 x1 = sX[sb][kg * (KH / 4) + k4];
        a0 = fmaf(w0, x0.x, a0); a0 = fmaf(w1, x0.y, a0);
        a0 = fmaf(w2, x0.z, a0); a0 = fmaf(w3, x0.w, a0);
        a1 = fmaf(w0, x1.x, a1); a1 = fmaf(w1, x1.y, a1);
        a1 = fmaf(w2, x1.z, a1); a1 = fmaf(w3, x1.w, a1);
    }
    if (kg >= 1) { sred[kg - 1][sa][tx] = a0; sred[kg - 1][sb][tx] = a1; }
    __syncthreads();
    if (kg == 0) {
        float bb = bias[o];
        float r0 = a0 + sred[0][sa][tx] + sred[1][sa][tx] + sred[2][sa][tx] + bb;
        float r1 = a1 + sred[0][sb][tx] + sred[1][sb][tx] + sred[2][sb][tx] + bb;
        Y[(size_t)(s0 + sa) * HH + o] = fmaxf(r0, 0.f);
        Y[(size_t)(s0 + sb) * HH + o] = fmaxf(r1, 0.f);
    }
}

// ---------------- root head GEMM: k-split partials ---------------------------
__global__ __launch_bounds__(512) void k_rootgemm(const float* __restrict__ W)
{
    constexpr int KH = HH / 4;
    __shared__ float4 sX[16][KH / 4];   // 8 KB

    int s0 = blockIdx.x * 16;
    int kq = blockIdx.y;
    int e  = threadIdx.x & 63;
    int sj = threadIdx.x >> 6;

    for (int i = threadIdx.x; i < 16 * (KH / 4); i += 512) {
        int s = i / (KH / 4), kk = i % (KH / 4);
        sX[s][kk] = reinterpret_cast<const float4*>(
            g_Y2 + (size_t)(s0 + s) * HH + kq * KH)[kk];
    }
    __syncthreads();

    const float* Wp = W + (size_t)kq * KH * EE + e;
    float a0 = 0.f, a1 = 0.f;
    int sa = sj * 2, sb = sj * 2 + 1;
#pragma unroll 8
    for (int k4 = 0; k4 < KH / 4; k4++) {
        float w0 = Wp[(size_t)(k4 * 4 + 0) * EE];
        float w1 = Wp[(size_t)(k4 * 4 + 1) * EE];
        float w2 = Wp[(size_t)(k4 * 4 + 2) * EE];
        float w3 = Wp[(size_t)(k4 * 4 + 3) * EE];
        float4 x0 = sX[sa][k4];
        float4 x1 = sX[sb][k4];
        a0 = fmaf(w0, x0.x, a0); a0 = fmaf(w1, x0.y, a0);
        a0 = fmaf(w2, x0.z, a0); a0 = fmaf(w3, x0.w, a0);
        a1 = fmaf(w0, x1.x, a1); a1 = fmaf(w1, x1.y, a1);
        a1 = fmaf(w2, x1.z, a1); a1 = fmaf(w3, x1.w, a1);
    }
    g_rp[(size_t)kq * BB * EE + (size_t)(s0 + sa) * EE + e] = a0;
    g_rp[(size_t)kq * BB * EE + (size_t)(s0 + sb) * EE + e] = a1;
}

// ---------------- root routing: warp per sample, grid 64 x 128 ---------------
__global__ __launch_bounds__(128) void k_route(const float* __restrict__ bias)
{
    int w = threadIdx.x >> 5;
    int l = threadIdx.x & 31;
    int b = blockIdx.x * 4 + w;

    int e0 = l, e1 = l + 32;
    float p00 = g_rp[(size_t)0 * BB * EE + (size_t)b * EE + e0];
    float p01 = g_rp[(size_t)1 * BB * EE + (size_t)b * EE + e0];
    float p02 = g_rp[(size_t)2 * BB * EE + (size_t)b * EE + e0];
    float p03 = g_rp[(size_t)3 * BB * EE + (size_t)b * EE + e0];
    float p10 = g_rp[(size_t)0 * BB * EE + (size_t)b * EE + e1];
    float p11 = g_rp[(size_t)1 * BB * EE + (size_t)b * EE + e1];
    float p12 = g_rp[(size_t)2 * BB * EE + (size_t)b * EE + e1];
    float p13 = g_rp[(size_t)3 * BB * EE + (size_t)b * EE + e1];
    float v0 = bias[e0] + (p00 + p01) + (p02 + p03);
    float v1 = bias[e1] + (p10 + p11) + (p12 + p13);

    unsigned long long k0 = ((unsigned long long)fkey(v0) << 32) | (unsigned int)(EE - 1 - e0);
    unsigned long long k1 = ((unsigned long long)fkey(v1) << 32) | (unsigned int)(EE - 1 - e1);
    unsigned long long best = max(k0, k1);
#pragma unroll
    for (int off = 16; off > 0; off >>= 1) {
        unsigned long long o2 = __shfl_down_sync(0xFFFFFFFFu, best, off);
        best = max(best, o2);
    }
    best = __shfl_sync(0xFFFFFFFFu, best, 0);
    float mx = funkey((unsigned int)(best >> 32));
    int   mi = EE - 1 - (int)(best & 0xFFFFFFFFu);

    float se = __expf(v0 - mx) + __expf(v1 - mx);
#pragma unroll
    for (int off = 16; off > 0; off >>= 1)
        se += __shfl_down_sync(0xFFFFFFFFu, se, off);

    if (l == 0) {
        g_bidx[b]   = mi;
        g_rootlp[b] = -__logf(se);       // lp at argmax = -log(sum exp(v-mx))
        int pos = atomicAdd(&g_count[mi], 1);
        g_slot[mi * BB + pos] = b;
    }
}

// ---------------- expert fma helper -----------------------------------------
__device__ __forceinline__ void fma4(float4& a, const float4 w, const float s)
{
    a.x = fmaf(w.x, s, a.x); a.y = fmaf(w.y, s, a.y);
    a.z = fmaf(w.z, s, a.z); a.w = fmaf(w.w, s, a.w);
}

// ---------------- grouped expert dense layer, balanced z tiles ---------------
// grid (EE, KS, NZ); 256 thr. Tile = 4 samples; block z handles tiles z, z+NZ...
// For OT=512 the 2 in-block k-subgroups write different partial slices.
template <int KDIM, int KS, int OT, int SRC, int DST, int NZ>
__global__ __launch_bounds__(256) void k_exp(
    const float* __restrict__ Xin, const float* __restrict__ Wsrc)
{
    constexpr int OTH  = OT / 4;        // 128 or 256
    constexpr int KSUB = 256 / OTH;     // 2 or 1
    constexpr int KR   = KDIM / KS;
    constexpr int KT   = KR / KSUB;

    const float* X = (SRC == 0) ? Xin : ((SRC == 1) ? g_h1 : g_h2);
    float* Pbase = (DST == 0) ? g_p1 : ((DST == 1) ? g_p2 : g_p3);

    int ex = blockIdx.x, ks = blockIdx.y, z = blockIdx.z;
    int c = g_count[ex];
    if (z * 4 >= c) return;

    int ot = threadIdx.x % OTH;
    int kg = threadIdx.x / OTH;
    int o  = ot * 4;
    int sxoff = kg * (KT / 4);

    const float* W = Wsrc + (size_t)ex * KDIM * OT + (size_t)(ks * KR + kg * KT) * OT;
    float* P = Pbase + (size_t)(ks * KSUB + kg) * BB * OT;

    __shared__ float4 sX[4][KR / 4];
    __shared__ int    sB[4];

    for (int st = z * 4; st < c; st += NZ * 4) {
        int ct = min(4, c - st);
        __syncthreads();
        if (threadIdx.x < 4)
            sB[threadIdx.x] = g_slot[ex * BB + st + ((threadIdx.x < ct) ? threadIdx.x : 0)];
        __syncthreads();
        for (int i = threadIdx.x; i < 4 * (KR / 4); i += 256) {
            int s = i / (KR / 4), kk = i % (KR / 4);
            sX[s][kk] = *reinterpret_cast<const float4*>(
                X + (size_t)sB[s] * KDIM + ks * KR + kk * 4);
        }
        __syncthreads();

        float4 acc[4];
#pragma unroll
        for (int j = 0; j < 4; j++) acc[j] = make_float4(0.f, 0.f, 0.f, 0.f);

#pragma unroll 8
        for (int k4 = 0; k4 < KT / 4; k4++) {
            const float* wp = W + (size_t)(k4 * 4) * OT + o;
            float4 w0 = *reinterpret_cast<const float4*>(wp);
            float4 w1 = *reinterpret_cast<const float4*>(wp + OT);
            float4 w2 = *reinterpret_cast<const float4*>(wp + 2 * OT);
            float4 w3 = *reinterpret_cast<const float4*>(wp + 3 * OT);
#pragma unroll
            for (int j = 0; j < 4; j++) {
                float4 x = sX[j][sxoff + k4];
                fma4(acc[j], w0, x.x);
                fma4(acc[j], w1, x.y);
                fma4(acc[j], w2, x.z);
                fma4(acc[j], w3, x.w);
            }
        }
#pragma unroll
        for (int j = 0; j < 4; j++)
            if (j < ct)
                *reinterpret_cast<float4*>(P + (size_t)sB[j] * OT + o) = acc[j];
    }
}

// ---------------- reduce 8 partials + bias + relu ----------------------------
template <int OT, int DST>
__global__ __launch_bounds__(256) void k_red(const float* __restrict__ ebias)
{
    const float* Pb = (DST == 0) ? g_p1 : g_p2;
    float* Y = (DST == 0) ? g_h1 : g_h2;
    int idx = blockIdx.x * 256 + threadIdx.x;          // float4 index
    const int row4 = OT / 4;
    int b = idx / row4, o4 = idx % row4;
    int o = o4 * 4;

    float4 s = *reinterpret_cast<const float4*>(Pb + (size_t)b * OT + o);
#pragma unroll
    for (int p = 1; p < 8; p++) {
        float4 v = *reinterpret_cast<const float4*>(Pb + ((size_t)p * BB + b) * OT + o);
        s.x += v.x; s.y += v.y; s.z += v.z; s.w += v.w;
    }
    float4 bb = *reinterpret_cast<const float4*>(ebias + (size_t)g_bidx[b] * OT + o);
    s.x = fmaxf(s.x + bb.x, 0.f);
    s.y = fmaxf(s.y + bb.y, 0.f);
    s.z = fmaxf(s.z + bb.z, 0.f);
    s.w = fmaxf(s.w + bb.w, 0.f);
    *reinterpret_cast<float4*>(Y + (size_t)b * OT + o) = s;
}

// ---------------- final: L3 reduce(8, float4) + log_softmax + top-11 --------
__global__ __launch_bounds__(256) void k_final(
    float* __restrict__ out, const float* __restrict__ eb3)
{
    int b = blockIdx.x;
    __shared__ __align__(16) float sv[NLF];
    __shared__ __align__(16) float orig[NLF];
    __shared__ unsigned long long swarp[8];
    __shared__ float sred[8];
    __shared__ float smx, slse;
    __shared__ int   chosen[KOUT + 1];

    int branch = g_bidx[b];
    int wid = threadIdx.x >> 5;
    int lane = threadIdx.x & 31;

    // vectorized reduce: thread t owns elements [4t, 4t+4) -> 9 float4 loads
    {
        int i4 = threadIdx.x * 4;
        float4 v = *reinterpret_cast<const float4*>(eb3 + (size_t)branch * NLF + i4);
#pragma unroll
        for (int p = 0; p < 8; p++) {
            float4 u = *reinterpret_cast<const float4*>(
                g_p3 + ((size_t)p * BB + b) * NLF + i4);
            v.x += u.x; v.y += u.y; v.z += u.z; v.w += u.w;
        }
        *reinterpret_cast<float4*>(sv + i4)   = v;
        *reinterpret_cast<float4*>(orig + i4) = v;
    }
    __syncthreads();

    for (int t = 0; t < KOUT + 1; t++) {
        unsigned long long best = 0ULL;
        for (int i = threadIdx.x; i < NLF; i += 256)
            best = max(best, ((unsigned long long)fkey(sv[i]) << 32) |
                             (unsigned int)(NLF - 1 - i));
#pragma unroll
        for (int off = 16; off > 0; off >>= 1) {
            unsigned long long o2 = __shfl_down_sync(0xFFFFFFFFu, best, off);
            best = max(best, o2);
        }
        if (lane == 0) swarp[wid] = best;
        __syncthreads();
        if (threadIdx.x == 0) {
            unsigned long long bb = swarp[0];
#pragma unroll
            for (int i2 = 1; i2 < 8; i2++) bb = max(bb, swarp[i2]);
            int idx = NLF - 1 - (int)(bb & 0xFFFFFFFFu);
            chosen[t] = idx;
            sv[idx] = -INFINITY;
            if (t == 0) smx = funkey((unsigned int)(bb >> 32));
        }
        __syncthreads();

        if (t == 0) {
            float mx = smx;
            float ls = 0.f;
            for (int i = threadIdx.x; i < NLF; i += 256)
                ls += __expf(orig[i] - mx);
#pragma unroll
            for (int off = 16; off > 0; off >>= 1)
                ls += __shfl_down_sync(0xFFFFFFFFu, ls, off);
            if (lane == 0) sred[wid] = ls;
            __syncthreads();
            if (threadIdx.x == 0) {
                float tot = 0.f;
#pragma unroll
                for (int i2 = 0; i2 < 8; i2++) tot += sred[i2];
                slse = mx + __logf(tot);
            }
            __syncthreads();
        }
    }

    if (threadIdx.x == 0) {
        float rlp   = g_rootlp[b];
        float lse   = slse;
        float* traj = out;                    // [B][K][2] as float
        float* flp  = out + BB * KOUT * 2;    // [B][K]
        int w = 0;
        for (int t = 0; t < KOUT + 1 && w < KOUT; t++) {
            int item = chosen[t];
            if (item == 0 && branch == 0) continue;   // drop id-0 trajectory
            traj[((size_t)b * KOUT + w) * 2 + 0] = (float)branch;
            traj[((size_t)b * KOUT + w) * 2 + 1] = (float)item;
            flp[(size_t)b * KOUT + w] = (orig[item] - lse) + rlp;
            w++;
        }
    }
}

// ---------------- launch ----------------------------------------------------
extern "C" void kernel_launch(void* const* d_in, const int* in_sizes, int n_in,
                              void* d_out, int out_size)
{
    const float* state = (const float*)d_in[0];
    const float* rW1   = (const float*)d_in[1];
    const float* rb1   = (const float*)d_in[2];
    const float* rW2   = (const float*)d_in[3];
    const float* rb2   = (const float*)d_in[4];
    const float* rW3   = (const float*)d_in[5];
    const float* rb3   = (const float*)d_in[6];
    const float* eW1   = (const float*)d_in[7];
    const float* eb1   = (const float*)d_in[8];
    const float* eW2   = (const float*)d_in[9];
    const float* eb2   = (const float*)d_in[10];
    const float* eW3   = (const float*)d_in[11];
    const float* eb3   = (const float*)d_in[12];
    float* out = (float*)d_out;

    k_rootlin<DD, 0, 0, true ><<<dim3(BB / 4, HH / 64), 512>>>(state, rW1, rb1);
    k_rootlin<HH, 1, 1, false><<<dim3(BB / 4, HH / 64), 512>>>(nullptr, rW2, rb2);
    k_rootgemm<<<dim3(BB / 16, 4), 512>>>(rW3);
    k_route<<<BB / 4, 128>>>(rb3);

    k_exp<DD, 4, HH,  0, 0, 4><<<dim3(EE, 4, 4), 256>>>(state,  eW1);
    k_red<HH, 0><<<(BB * HH / 4) / 256, 256>>>(eb1);
    k_exp<HH, 4, HH,  1, 1, 4><<<dim3(EE, 4, 4), 256>>>(nullptr, eW2);
    k_red<HH, 1><<<(BB * HH / 4) / 256, 256>>>(eb2);
    k_exp<HH, 8, NLF, 2, 2, 4><<<dim3(EE, 8, 4), 256>>>(nullptr, eW3);
    k_final<<<BB, 256>>>(out, eb3);
}

// round 15
// speedup vs baseline: 1.3014x; 1.0314x over previous
#include <cuda_runtime.h>
#include <math.h>

#define BB   256
#define DD   256
#define HH   512
#define EE   64
#define NLF  1024
#define KOUT 10

// ---------------- scratch (device globals; no allocation allowed) ----------
__device__ float g_Y1[BB * HH];
__device__ float g_Y2[BB * HH];
__device__ float g_h1[BB * HH];
__device__ float g_h2[BB * HH];
__device__ int   g_bidx[BB];
__device__ float g_rootlp[BB];
__device__ int   g_count[EE];
__device__ int   g_slot[EE * BB];
__device__ float g_rp[8 * BB * EE];     // root-head k-split partials (8-way)
// expert k-split partial sums (deterministic; no float atomics)
__device__ float g_p1[8 * BB * HH];     // 4 MB
__device__ float g_p2[8 * BB * HH];     // 4 MB
__device__ float g_p3[8 * BB * NLF];    // 8 MB

// ---------------- orderable packing helpers ---------------------------------
__device__ __forceinline__ unsigned int fkey(float v)
{
    unsigned int b = __float_as_uint(v);
    return (b & 0x80000000u) ? ~b : (b | 0x80000000u);
}
__device__ __forceinline__ float funkey(unsigned int b)
{
    return __uint_as_float((b & 0x80000000u) ? (b & 0x7FFFFFFFu) : ~b);
}

// ---------------- root dense layers: 4 samples/block, 4-way k-split ---------
// grid (B/4, H/64), 512 thr: o(64) x sg(2, 2 samples each) x kg(4)
template <int KDIM, int SRCSEL, int DSTSEL, bool ZERO>
__global__ __launch_bounds__(512) void k_rootlin(
    const float* __restrict__ Xin, const float* __restrict__ W,
    const float* __restrict__ bias)
{
    const float* X = (SRCSEL == 0) ? Xin : g_Y1;
    float* Y = (DSTSEL == 0) ? g_Y1 : g_Y2;
    constexpr int KH = KDIM / 4;

    if (ZERO && blockIdx.x == 0 && blockIdx.y == 0 && threadIdx.x < EE)
        g_count[threadIdx.x] = 0;

    __shared__ float4 sX[4][KDIM / 4];
    __shared__ float  sred[3][4][64];

    int s0 = blockIdx.x * 4;
    int tx = threadIdx.x & 63;
    int sg = (threadIdx.x >> 6) & 1;
    int kg = threadIdx.x >> 7;            // 0..3
    int o  = blockIdx.y * 64 + tx;

    for (int i = threadIdx.x; i < 4 * (KDIM / 4); i += 512) {
        int s = i / (KDIM / 4), kk = i % (KDIM / 4);
        sX[s][kk] = reinterpret_cast<const float4*>(X + (size_t)(s0 + s) * KDIM)[kk];
    }
    __syncthreads();

    const float* Wp = W + (size_t)kg * KH * HH + o;
    float a0 = 0.f, a1 = 0.f;
    int sa = sg * 2, sb = sg * 2 + 1;
#pragma unroll 8
    for (int k4 = 0; k4 < KH / 4; k4++) {
        float w0 = Wp[(size_t)(k4 * 4 + 0) * HH];
        float w1 = Wp[(size_t)(k4 * 4 + 1) * HH];
        float w2 = Wp[(size_t)(k4 * 4 + 2) * HH];
        float w3 = Wp[(size_t)(k4 * 4 + 3) * HH];
        float4 x0 = sX[sa][kg * (KH / 4) + k4];
        float4 x1 = sX[sb][kg * (KH / 4) + k4];
        a0 = fmaf(w0, x0.x, a0); a0 = fmaf(w1, x0.y, a0);
        a0 = fmaf(w2, x0.z, a0); a0 = fmaf(w3, x0.w, a0);
        a1 = fmaf(w0, x1.x, a1); a1 = fmaf(w1, x1.y, a1);
        a1 = fmaf(w2, x1.z, a1); a1 = fmaf(w3, x1.w, a1);
    }
    if (kg >= 1) { sred[kg - 1][sa][tx] = a0; sred[kg - 1][sb][tx] = a1; }
    __syncthreads();
    if (kg == 0) {
        float bb = bias[o];
        float r0 = a0 + sred[0][sa][tx] + sred[1][sa][tx] + sred[2][sa][tx] + bb;
        float r1 = a1 + sred[0][sb][tx] + sred[1][sb][tx] + sred[2][sb][tx] + bb;
        Y[(size_t)(s0 + sa) * HH + o] = fmaxf(r0, 0.f);
        Y[(size_t)(s0 + sb) * HH + o] = fmaxf(r1, 0.f);
    }
}

// ---------------- root head GEMM: 8 samples/block, 8-way k-split ------------
// grid (B/8, 8) = 256 blocks, 512 thr: e(64) x sj(8, 1 sample each); KH=64
__global__ __launch_bounds__(512) void k_rootgemm(const float* __restrict__ W)
{
    constexpr int KH = HH / 8;           // 64
    __shared__ float4 sX[8][KH / 4];     // 2 KB

    int s0 = blockIdx.x * 8;
    int kq = blockIdx.y;                 // 0..7
    int e  = threadIdx.x & 63;
    int sj = threadIdx.x >> 6;           // 0..7

    for (int i = threadIdx.x; i < 8 * (KH / 4); i += 512) {
        int s = i / (KH / 4), kk = i % (KH / 4);
        sX[s][kk] = reinterpret_cast<const float4*>(
            g_Y2 + (size_t)(s0 + s) * HH + kq * KH)[kk];
    }
    __syncthreads();

    const float* Wp = W + (size_t)kq * KH * EE + e;
    float a0 = 0.f;
#pragma unroll 16
    for (int k4 = 0; k4 < KH / 4; k4++) {
        float w0 = Wp[(size_t)(k4 * 4 + 0) * EE];
        float w1 = Wp[(size_t)(k4 * 4 + 1) * EE];
        float w2 = Wp[(size_t)(k4 * 4 + 2) * EE];
        float w3 = Wp[(size_t)(k4 * 4 + 3) * EE];
        float4 x0 = sX[sj][k4];
        a0 = fmaf(w0, x0.x, a0); a0 = fmaf(w1, x0.y, a0);
        a0 = fmaf(w2, x0.z, a0); a0 = fmaf(w3, x0.w, a0);
    }
    g_rp[(size_t)kq * BB * EE + (size_t)(s0 + sj) * EE + e] = a0;
}

// ---------------- root routing: warp per sample, grid 64 x 128 ---------------
__global__ __launch_bounds__(128) void k_route(const float* __restrict__ bias)
{
    int w = threadIdx.x >> 5;
    int l = threadIdx.x & 31;
    int b = blockIdx.x * 4 + w;

    int e0 = l, e1 = l + 32;
    float v0 = bias[e0], v1 = bias[e1];
    float s00 = 0.f, s01 = 0.f, s10 = 0.f, s11 = 0.f;
#pragma unroll
    for (int p = 0; p < 8; p += 2) {
        s00 += g_rp[(size_t)p * BB * EE + (size_t)b * EE + e0];
        s01 += g_rp[(size_t)(p + 1) * BB * EE + (size_t)b * EE + e0];
        s10 += g_rp[(size_t)p * BB * EE + (size_t)b * EE + e1];
        s11 += g_rp[(size_t)(p + 1) * BB * EE + (size_t)b * EE + e1];
    }
    v0 += s00 + s01;
    v1 += s10 + s11;

    unsigned long long k0 = ((unsigned long long)fkey(v0) << 32) | (unsigned int)(EE - 1 - e0);
    unsigned long long k1 = ((unsigned long long)fkey(v1) << 32) | (unsigned int)(EE - 1 - e1);
    unsigned long long best = max(k0, k1);
#pragma unroll
    for (int off = 16; off > 0; off >>= 1) {
        unsigned long long o2 = __shfl_down_sync(0xFFFFFFFFu, best, off);
        best = max(best, o2);
    }
    best = __shfl_sync(0xFFFFFFFFu, best, 0);
    float mx = funkey((unsigned int)(best >> 32));
    int   mi = EE - 1 - (int)(best & 0xFFFFFFFFu);

    float se = __expf(v0 - mx) + __expf(v1 - mx);
#pragma unroll
    for (int off = 16; off > 0; off >>= 1)
        se += __shfl_down_sync(0xFFFFFFFFu, se, off);

    if (l == 0) {
        g_bidx[b]   = mi;
        g_rootlp[b] = -__logf(se);       // lp at argmax = -log(sum exp(v-mx))
        int pos = atomicAdd(&g_count[mi], 1);
        g_slot[mi * BB + pos] = b;
    }
}

// ---------------- expert fma helper -----------------------------------------
__device__ __forceinline__ void fma4(float4& a, const float4 w, const float s)
{
    a.x = fmaf(w.x, s, a.x); a.y = fmaf(w.y, s, a.y);
    a.z = fmaf(w.z, s, a.z); a.w = fmaf(w.w, s, a.w);
}

// ---------------- grouped expert dense layer, balanced z tiles ---------------
// grid (EE, KS, NZ); 256 thr. Tile = 4 samples; block z handles tiles z, z+NZ...
// For OT=512 the 2 in-block k-subgroups write different partial slices.
template <int KDIM, int KS, int OT, int SRC, int DST, int NZ>
__global__ __launch_bounds__(256) void k_exp(
    const float* __restrict__ Xin, const float* __restrict__ Wsrc)
{
    constexpr int OTH  = OT / 4;        // 128 or 256
    constexpr int KSUB = 256 / OTH;     // 2 or 1
    constexpr int KR   = KDIM / KS;
    constexpr int KT   = KR / KSUB;

    const float* X = (SRC == 0) ? Xin : ((SRC == 1) ? g_h1 : g_h2);
    float* Pbase = (DST == 0) ? g_p1 : ((DST == 1) ? g_p2 : g_p3);

    int ex = blockIdx.x, ks = blockIdx.y, z = blockIdx.z;
    int c = g_count[ex];
    if (z * 4 >= c) return;

    int ot = threadIdx.x % OTH;
    int kg = threadIdx.x / OTH;
    int o  = ot * 4;
    int sxoff = kg * (KT / 4);

    const float* W = Wsrc + (size_t)ex * KDIM * OT + (size_t)(ks * KR + kg * KT) * OT;
    float* P = Pbase + (size_t)(ks * KSUB + kg) * BB * OT;

    __shared__ float4 sX[4][KR / 4];
    __shared__ int    sB[4];

    for (int st = z * 4; st < c; st += NZ * 4) {
        int ct = min(4, c - st);
        __syncthreads();
        if (threadIdx.x < 4)
            sB[threadIdx.x] = g_slot[ex * BB + st + ((threadIdx.x < ct) ? threadIdx.x : 0)];
        __syncthreads();
        for (int i = threadIdx.x; i < 4 * (KR / 4); i += 256) {
            int s = i / (KR / 4), kk = i % (KR / 4);
            sX[s][kk] = *reinterpret_cast<const float4*>(
                X + (size_t)sB[s] * KDIM + ks * KR + kk * 4);
        }
        __syncthreads();

        float4 acc[4];
#pragma unroll
        for (int j = 0; j < 4; j++) acc[j] = make_float4(0.f, 0.f, 0.f, 0.f);

#pragma unroll 8
        for (int k4 = 0; k4 < KT / 4; k4++) {
            const float* wp = W + (size_t)(k4 * 4) * OT + o;
            float4 w0 = *reinterpret_cast<const float4*>(wp);
            float4 w1 = *reinterpret_cast<const float4*>(wp + OT);
            float4 w2 = *reinterpret_cast<const float4*>(wp + 2 * OT);
            float4 w3 = *reinterpret_cast<const float4*>(wp + 3 * OT);
#pragma unroll
            for (int j = 0; j < 4; j++) {
                float4 x = sX[j][sxoff + k4];
                fma4(acc[j], w0, x.x);
                fma4(acc[j], w1, x.y);
                fma4(acc[j], w2, x.z);
                fma4(acc[j], w3, x.w);
            }
        }
#pragma unroll
        for (int j = 0; j < 4; j++)
            if (j < ct)
                *reinterpret_cast<float4*>(P + (size_t)sB[j] * OT + o) = acc[j];
    }
}

// ---------------- reduce 8 partials + bias + relu ----------------------------
template <int OT, int DST>
__global__ __launch_bounds__(256) void k_red(const float* __restrict__ ebias)
{
    const float* Pb = (DST == 0) ? g_p1 : g_p2;
    float* Y = (DST == 0) ? g_h1 : g_h2;
    int idx = blockIdx.x * 256 + threadIdx.x;          // float4 index
    const int row4 = OT / 4;
    int b = idx / row4, o4 = idx % row4;
    int o = o4 * 4;

    float4 s = *reinterpret_cast<const float4*>(Pb + (size_t)b * OT + o);
#pragma unroll
    for (int p = 1; p < 8; p++) {
        float4 v = *reinterpret_cast<const float4*>(Pb + ((size_t)p * BB + b) * OT + o);
        s.x += v.x; s.y += v.y; s.z += v.z; s.w += v.w;
    }
    float4 bb = *reinterpret_cast<const float4*>(ebias + (size_t)g_bidx[b] * OT + o);
    s.x = fmaxf(s.x + bb.x, 0.f);
    s.y = fmaxf(s.y + bb.y, 0.f);
    s.z = fmaxf(s.z + bb.z, 0.f);
    s.w = fmaxf(s.w + bb.w, 0.f);
    *reinterpret_cast<float4*>(Y + (size_t)b * OT + o) = s;
}

// ---------------- final: L3 reduce(8, float4) + log_softmax + top-11 --------
__global__ __launch_bounds__(256) void k_final(
    float* __restrict__ out, const float* __restrict__ eb3)
{
    int b = blockIdx.x;
    __shared__ __align__(16) float sv[NLF];
    __shared__ __align__(16) float orig[NLF];
    __shared__ unsigned long long swarp[8];
    __shared__ float sred[8];
    __shared__ float smx, slse;
    __shared__ int   chosen[KOUT + 1];

    int branch = g_bidx[b];
    int wid = threadIdx.x >> 5;
    int lane = threadIdx.x & 31;

    // vectorized reduce: thread t owns elements [4t, 4t+4) -> 9 float4 loads
    {
        int i4 = threadIdx.x * 4;
        float4 v = *reinterpret_cast<const float4*>(eb3 + (size_t)branch * NLF + i4);
#pragma unroll
        for (int p = 0; p < 8; p++) {
            float4 u = *reinterpret_cast<const float4*>(
                g_p3 + ((size_t)p * BB + b) * NLF + i4);
            v.x += u.x; v.y += u.y; v.z += u.z; v.w += u.w;
        }
        *reinterpret_cast<float4*>(sv + i4)   = v;
        *reinterpret_cast<float4*>(orig + i4) = v;
    }
    __syncthreads();

    for (int t = 0; t < KOUT + 1; t++) {
        unsigned long long best = 0ULL;
        for (int i = threadIdx.x; i < NLF; i += 256)
            best = max(best, ((unsigned long long)fkey(sv[i]) << 32) |
                             (unsigned int)(NLF - 1 - i));
#pragma unroll
        for (int off = 16; off > 0; off >>= 1) {
            unsigned long long o2 = __shfl_down_sync(0xFFFFFFFFu, best, off);
            best = max(best, o2);
        }
        if (lane == 0) swarp[wid] = best;
        __syncthreads();
        if (threadIdx.x == 0) {
            unsigned long long bb = swarp[0];
#pragma unroll
            for (int i2 = 1; i2 < 8; i2++) bb = max(bb, swarp[i2]);
            int idx = NLF - 1 - (int)(bb & 0xFFFFFFFFu);
            chosen[t] = idx;
            sv[idx] = -INFINITY;
            if (t == 0) smx = funkey((unsigned int)(bb >> 32));
        }
        __syncthreads();

        if (t == 0) {
            float mx = smx;
            float ls = 0.f;
            for (int i = threadIdx.x; i < NLF; i += 256)
                ls += __expf(orig[i] - mx);
#pragma unroll
            for (int off = 16; off > 0; off >>= 1)
                ls += __shfl_down_sync(0xFFFFFFFFu, ls, off);
            if (lane == 0) sred[wid] = ls;
            __syncthreads();
            if (threadIdx.x == 0) {
                float tot = 0.f;
#pragma unroll
                for (int i2 = 0; i2 < 8; i2++) tot += sred[i2];
                slse = mx + __logf(tot);
            }
            __syncthreads();
        }
    }

    if (threadIdx.x == 0) {
        float rlp   = g_rootlp[b];
        float lse   = slse;
        float* traj = out;                    // [B][K][2] as float
        float* flp  = out + BB * KOUT * 2;    // [B][K]
        int w = 0;
        for (int t = 0; t < KOUT + 1 && w < KOUT; t++) {
            int item = chosen[t];
            if (item == 0 && branch == 0) continue;   // drop id-0 trajectory
            traj[((size_t)b * KOUT + w) * 2 + 0] = (float)branch;
            traj[((size_t)b * KOUT + w) * 2 + 1] = (float)item;
            flp[(size_t)b * KOUT + w] = (orig[item] - lse) + rlp;
            w++;
        }
    }
}

// ---------------- launch ----------------------------------------------------
extern "C" void kernel_launch(void* const* d_in, const int* in_sizes, int n_in,
                              void* d_out, int out_size)
{
    const float* state = (const float*)d_in[0];
    const float* rW1   = (const float*)d_in[1];
    const float* rb1   = (const float*)d_in[2];
    const float* rW2   = (const float*)d_in[3];
    const float* rb2   = (const float*)d_in[4];
    const float* rW3   = (const float*)d_in[5];
    const float* rb3   = (const float*)d_in[6];
    const float* eW1   = (const float*)d_in[7];
    const float* eb1   = (const float*)d_in[8];
    const float* eW2   = (const float*)d_in[9];
    const float* eb2   = (const float*)d_in[10];
    const float* eW3   = (const float*)d_in[11];
    const float* eb3   = (const float*)d_in[12];
    float* out = (float*)d_out;

    k_rootlin<DD, 0, 0, true ><<<dim3(BB / 4, HH / 64), 512>>>(state, rW1, rb1);
    k_rootlin<HH, 1, 1, false><<<dim3(BB / 4, HH / 64), 512>>>(nullptr, rW2, rb2);
    k_rootgemm<<<dim3(BB / 8, 8), 512>>>(rW3);
    k_route<<<BB / 4, 128>>>(rb3);

    k_exp<DD, 4, HH,  0, 0, 4><<<dim3(EE, 4, 4), 256>>>(state,  eW1);
    k_red<HH, 0><<<(BB * HH / 4) / 256, 256>>>(eb1);
    k_exp<HH, 4, HH,  1, 1, 4><<<dim3(EE, 4, 4), 256>>>(nullptr, eW2);
    k_red<HH, 1><<<(BB * HH / 4) / 256, 256>>>(eb2);
    k_exp<HH, 8, NLF, 2, 2, 4><<<dim3(EE, 8, 4), 256>>>(nullptr, eW3);
    k_final<<<BB, 256>>>(out, eb3);
}

// round 17
// speedup vs baseline: 1.3249x; 1.0180x over previous
#include <cuda_runtime.h>
#include <math.h>

#define BB   256
#define DD   256
#define HH   512
#define EE   64
#define NLF  1024
#define KOUT 10

// ---------------- scratch (device globals; no allocation allowed) ----------
__device__ float g_Y1[BB * HH];
__device__ float g_Y2[BB * HH];
__device__ float g_h1[BB * HH];
__device__ float g_h2[BB * HH];
__device__ int   g_bidx[BB];
__device__ float g_rootlp[BB];
__device__ int   g_count[EE];
__device__ int   g_slot[EE * BB];
// expert k-split partial sums (deterministic; no float atomics)
__device__ float g_p1[8 * BB * HH];     // 4 MB
__device__ float g_p2[8 * BB * HH];     // 4 MB
__device__ float g_p3[8 * BB * NLF];    // 8 MB

// ---------------- orderable packing helpers ---------------------------------
__device__ __forceinline__ unsigned int fkey(float v)
{
    unsigned int b = __float_as_uint(v);
    return (b & 0x80000000u) ? ~b : (b | 0x80000000u);
}
__device__ __forceinline__ float funkey(unsigned int b)
{
    return __uint_as_float((b & 0x80000000u) ? (b & 0x7FFFFFFFu) : ~b);
}

// ---------------- root dense layers: 4 samples/block, 4-way k-split ---------
// grid (B/4, H/64), 512 thr: o(64) x sg(2, 2 samples each) x kg(4)
template <int KDIM, int SRCSEL, int DSTSEL, bool ZERO>
__global__ __launch_bounds__(512) void k_rootlin(
    const float* __restrict__ Xin, const float* __restrict__ W,
    const float* __restrict__ bias)
{
    const float* X = (SRCSEL == 0) ? Xin : g_Y1;
    float* Y = (DSTSEL == 0) ? g_Y1 : g_Y2;
    constexpr int KH = KDIM / 4;

    if (ZERO && blockIdx.x == 0 && blockIdx.y == 0 && threadIdx.x < EE)
        g_count[threadIdx.x] = 0;

    __shared__ float4 sX[4][KDIM / 4];
    __shared__ float  sred[3][4][64];

    int s0 = blockIdx.x * 4;
    int tx = threadIdx.x & 63;
    int sg = (threadIdx.x >> 6) & 1;
    int kg = threadIdx.x >> 7;            // 0..3
    int o  = blockIdx.y * 64 + tx;

    for (int i = threadIdx.x; i < 4 * (KDIM / 4); i += 512) {
        int s = i / (KDIM / 4), kk = i % (KDIM / 4);
        sX[s][kk] = reinterpret_cast<const float4*>(X + (size_t)(s0 + s) * KDIM)[kk];
    }
    __syncthreads();

    const float* Wp = W + (size_t)kg * KH * HH + o;
    float a0 = 0.f, a1 = 0.f;
    int sa = sg * 2, sb = sg * 2 + 1;
#pragma unroll 8
    for (int k4 = 0; k4 < KH / 4; k4++) {
        float w0 = Wp[(size_t)(k4 * 4 + 0) * HH];
        float w1 = Wp[(size_t)(k4 * 4 + 1) * HH];
        float w2 = Wp[(size_t)(k4 * 4 + 2) * HH];
        float w3 = Wp[(size_t)(k4 * 4 + 3) * HH];
        float4 x0 = sX[sa][kg * (KH / 4) + k4];
        float4 x1 = sX[sb][kg * (KH / 4) + k4];
        a0 = fmaf(w0, x0.x, a0); a0 = fmaf(w1, x0.y, a0);
        a0 = fmaf(w2, x0.z, a0); a0 = fmaf(w3, x0.w, a0);
        a1 = fmaf(w0, x1.x, a1); a1 = fmaf(w1, x1.y, a1);
        a1 = fmaf(w2, x1.z, a1); a1 = fmaf(w3, x1.w, a1);
    }
    if (kg >= 1) { sred[kg - 1][sa][tx] = a0; sred[kg - 1][sb][tx] = a1; }
    __syncthreads();
    if (kg == 0) {
        float bb = bias[o];
        float r0 = a0 + sred[0][sa][tx] + sred[1][sa][tx] + sred[2][sa][tx] + bb;
        float r1 = a1 + sred[0][sb][tx] + sred[1][sb][tx] + sred[2][sb][tx] + bb;
        Y[(size_t)(s0 + sa) * HH + o] = fmaxf(r0, 0.f);
        Y[(size_t)(s0 + sb) * HH + o] = fmaxf(r1, 0.f);
    }
}

// ---------------- fused root head: 1 sample/block, GEMM + routing -----------
// grid (B) = 256 blocks, 512 thr: e(64) x kq(8); W3 (128 KB) is L2-resident.
__global__ __launch_bounds__(512) void k_roothead(
    const float* __restrict__ W, const float* __restrict__ bias)
{
    constexpr int KH = HH / 8;           // 64
    __shared__ float4 sX[HH / 4];        // 2 KB
    __shared__ float  sred[8][EE];       // 2 KB

    int b  = blockIdx.x;
    int e  = threadIdx.x & 63;
    int kq = threadIdx.x >> 6;           // 0..7

    if (threadIdx.x < HH / 4)
        sX[threadIdx.x] = reinterpret_cast<const float4*>(g_Y2 + (size_t)b * HH)[threadIdx.x];
    __syncthreads();

    const float* Wp = W + (size_t)kq * KH * EE + e;
    float a0 = 0.f;
#pragma unroll 16
    for (int k4 = 0; k4 < KH / 4; k4++) {
        float w0 = Wp[(size_t)(k4 * 4 + 0) * EE];
        float w1 = Wp[(size_t)(k4 * 4 + 1) * EE];
        float w2 = Wp[(size_t)(k4 * 4 + 2) * EE];
        float w3 = Wp[(size_t)(k4 * 4 + 3) * EE];
        float4 x = sX[kq * (KH / 4) + k4];
        a0 = fmaf(w0, x.x, a0); a0 = fmaf(w1, x.y, a0);
        a0 = fmaf(w2, x.z, a0); a0 = fmaf(w3, x.w, a0);
    }
    sred[kq][e] = a0;
    __syncthreads();

    // warp 0: reduce 8 k-groups, argmax + log_softmax + routing
    if (threadIdx.x < 32) {
        int l = threadIdx.x;
        int e0 = l, e1 = l + 32;
        float v0 = bias[e0], v1 = bias[e1];
#pragma unroll
        for (int p = 0; p < 8; p++) { v0 += sred[p][e0]; v1 += sred[p][e1]; }

        unsigned long long k0 = ((unsigned long long)fkey(v0) << 32) | (unsigned int)(EE - 1 - e0);
        unsigned long long k1 = ((unsigned long long)fkey(v1) << 32) | (unsigned int)(EE - 1 - e1);
        unsigned long long best = max(k0, k1);
#pragma unroll
        for (int off = 16; off > 0; off >>= 1) {
            unsigned long long o2 = __shfl_down_sync(0xFFFFFFFFu, best, off);
            best = max(best, o2);
        }
        best = __shfl_sync(0xFFFFFFFFu, best, 0);
        float mx = funkey((unsigned int)(best >> 32));
        int   mi = EE - 1 - (int)(best & 0xFFFFFFFFu);

        float se = __expf(v0 - mx) + __expf(v1 - mx);
#pragma unroll
        for (int off = 16; off > 0; off >>= 1)
            se += __shfl_down_sync(0xFFFFFFFFu, se, off);

        if (l == 0) {
            g_bidx[b]   = mi;
            g_rootlp[b] = -__logf(se);   // lp at argmax = -log(sum exp(v-mx))
            int pos = atomicAdd(&g_count[mi], 1);
            g_slot[mi * BB + pos] = b;
        }
    }
}

// ---------------- expert fma helper -----------------------------------------
__device__ __forceinline__ void fma4(float4& a, const float4 w, const float s)
{
    a.x = fmaf(w.x, s, a.x); a.y = fmaf(w.y, s, a.y);
    a.z = fmaf(w.z, s, a.z); a.w = fmaf(w.w, s, a.w);
}

// ---------------- grouped expert dense layer, balanced z tiles ---------------
// grid (EE, KS, NZ); 256 thr. Tile = 4 samples; block z handles tiles z, z+NZ...
// For OT=512 the 2 in-block k-subgroups write different partial slices.
template <int KDIM, int KS, int OT, int SRC, int DST, int NZ>
__global__ __launch_bounds__(256) void k_exp(
    const float* __restrict__ Xin, const float* __restrict__ Wsrc)
{
    constexpr int OTH  = OT / 4;        // 128 or 256
    constexpr int KSUB = 256 / OTH;     // 2 or 1
    constexpr int KR   = KDIM / KS;
    constexpr int KT   = KR / KSUB;

    const float* X = (SRC == 0) ? Xin : ((SRC == 1) ? g_h1 : g_h2);
    float* Pbase = (DST == 0) ? g_p1 : ((DST == 1) ? g_p2 : g_p3);

    int ex = blockIdx.x, ks = blockIdx.y, z = blockIdx.z;
    int c = g_count[ex];
    if (z * 4 >= c) return;

    int ot = threadIdx.x % OTH;
    int kg = threadIdx.x / OTH;
    int o  = ot * 4;
    int sxoff = kg * (KT / 4);

    const float* W = Wsrc + (size_t)ex * KDIM * OT + (size_t)(ks * KR + kg * KT) * OT;
    float* P = Pbase + (size_t)(ks * KSUB + kg) * BB * OT;

    __shared__ float4 sX[4][KR / 4];
    __shared__ int    sB[4];

    for (int st = z * 4; st < c; st += NZ * 4) {
        int ct = min(4, c - st);
        __syncthreads();
        if (threadIdx.x < 4)
            sB[threadIdx.x] = g_slot[ex * BB + st + ((threadIdx.x < ct) ? threadIdx.x : 0)];
        __syncthreads();
        for (int i = threadIdx.x; i < 4 * (KR / 4); i += 256) {
            int s = i / (KR / 4), kk = i % (KR / 4);
            sX[s][kk] = *reinterpret_cast<const float4*>(
                X + (size_t)sB[s] * KDIM + ks * KR + kk * 4);
        }
        __syncthreads();

        float4 acc[4];
#pragma unroll
        for (int j = 0; j < 4; j++) acc[j] = make_float4(0.f, 0.f, 0.f, 0.f);

#pragma unroll 8
        for (int k4 = 0; k4 < KT / 4; k4++) {
            const float* wp = W + (size_t)(k4 * 4) * OT + o;
            float4 w0 = *reinterpret_cast<const float4*>(wp);
            float4 w1 = *reinterpret_cast<const float4*>(wp + OT);
            float4 w2 = *reinterpret_cast<const float4*>(wp + 2 * OT);
            float4 w3 = *reinterpret_cast<const float4*>(wp + 3 * OT);
#pragma unroll
            for (int j = 0; j < 4; j++) {
                float4 x = sX[j][sxoff + k4];
                fma4(acc[j], w0, x.x);
                fma4(acc[j], w1, x.y);
                fma4(acc[j], w2, x.z);
                fma4(acc[j], w3, x.w);
            }
        }
#pragma unroll
        for (int j = 0; j < 4; j++)
            if (j < ct)
                *reinterpret_cast<float4*>(P + (size_t)sB[j] * OT + o) = acc[j];
    }
}

// ---------------- reduce 8 partials + bias + relu ----------------------------
template <int OT, int DST>
__global__ __launch_bounds__(256) void k_red(const float* __restrict__ ebias)
{
    const float* Pb = (DST == 0) ? g_p1 : g_p2;
    float* Y = (DST == 0) ? g_h1 : g_h2;
    int idx = blockIdx.x * 256 + threadIdx.x;          // float4 index
    const int row4 = OT / 4;
    int b = idx / row4, o4 = idx % row4;
    int o = o4 * 4;

    float4 s = *reinterpret_cast<const float4*>(Pb + (size_t)b * OT + o);
#pragma unroll
    for (int p = 1; p < 8; p++) {
        float4 v = *reinterpret_cast<const float4*>(Pb + ((size_t)p * BB + b) * OT + o);
        s.x += v.x; s.y += v.y; s.z += v.z; s.w += v.w;
    }
    float4 bb = *reinterpret_cast<const float4*>(ebias + (size_t)g_bidx[b] * OT + o);
    s.x = fmaxf(s.x + bb.x, 0.f);
    s.y = fmaxf(s.y + bb.y, 0.f);
    s.z = fmaxf(s.z + bb.z, 0.f);
    s.w = fmaxf(s.w + bb.w, 0.f);
    *reinterpret_cast<float4*>(Y + (size_t)b * OT + o) = s;
}

// ---------------- final: L3 reduce(8, float4) + log_softmax + top-11 --------
__global__ __launch_bounds__(256) void k_final(
    float* __restrict__ out, const float* __restrict__ eb3)
{
    int b = blockIdx.x;
    __shared__ __align__(16) float sv[NLF];
    __shared__ __align__(16) float orig[NLF];
    __shared__ unsigned long long swarp[8];
    __shared__ float sred[8];
    __shared__ float smx, slse;
    __shared__ int   chosen[KOUT + 1];

    int branch = g_bidx[b];
    int wid = threadIdx.x >> 5;
    int lane = threadIdx.x & 31;

    // vectorized reduce: thread t owns elements [4t, 4t+4) -> 9 float4 loads
    {
        int i4 = threadIdx.x * 4;
        float4 v = *reinterpret_cast<const float4*>(eb3 + (size_t)branch * NLF + i4);
#pragma unroll
        for (int p = 0; p < 8; p++) {
            float4 u = *reinterpret_cast<const float4*>(
                g_p3 + ((size_t)p * BB + b) * NLF + i4);
            v.x += u.x; v.y += u.y; v.z += u.z; v.w += u.w;
        }
        *reinterpret_cast<float4*>(sv + i4)   = v;
        *reinterpret_cast<float4*>(orig + i4) = v;
    }
    __syncthreads();

    for (int t = 0; t < KOUT + 1; t++) {
        unsigned long long best = 0ULL;
        for (int i = threadIdx.x; i < NLF; i += 256)
            best = max(best, ((unsigned long long)fkey(sv[i]) << 32) |
                             (unsigned int)(NLF - 1 - i));
#pragma unroll
        for (int off = 16; off > 0; off >>= 1) {
            unsigned long long o2 = __shfl_down_sync(0xFFFFFFFFu, best, off);
            best = max(best, o2);
        }
        if (lane == 0) swarp[wid] = best;
        __syncthreads();
        if (threadIdx.x == 0) {
            unsigned long long bb = swarp[0];
#pragma unroll
            for (int i2 = 1; i2 < 8; i2++) bb = max(bb, swarp[i2]);
            int idx = NLF - 1 - (int)(bb & 0xFFFFFFFFu);
            chosen[t] = idx;
            sv[idx] = -INFINITY;
            if (t == 0) smx = funkey((unsigned int)(bb >> 32));
        }
        __syncthreads();

        if (t == 0) {
            float mx = smx;
            float ls = 0.f;
            for (int i = threadIdx.x; i < NLF; i += 256)
                ls += __expf(orig[i] - mx);
#pragma unroll
            for (int off = 16; off > 0; off >>= 1)
                ls += __shfl_down_sync(0xFFFFFFFFu, ls, off);
            if (lane == 0) sred[wid] = ls;
            __syncthreads();
            if (threadIdx.x == 0) {
                float tot = 0.f;
#pragma unroll
                for (int i2 = 0; i2 < 8; i2++) tot += sred[i2];
                slse = mx + __logf(tot);
            }
            __syncthreads();
        }
    }

    if (threadIdx.x == 0) {
        float rlp   = g_rootlp[b];
        float lse   = slse;
        float* traj = out;                    // [B][K][2] as float
        float* flp  = out + BB * KOUT * 2;    // [B][K]
        int w = 0;
        for (int t = 0; t < KOUT + 1 && w < KOUT; t++) {
            int item = chosen[t];
            if (item == 0 && branch == 0) continue;   // drop id-0 trajectory
            traj[((size_t)b * KOUT + w) * 2 + 0] = (float)branch;
            traj[((size_t)b * KOUT + w) * 2 + 1] = (float)item;
            flp[(size_t)b * KOUT + w] = (orig[item] - lse) + rlp;
            w++;
        }
    }
}

// ---------------- launch ----------------------------------------------------
extern "C" void kernel_launch(void* const* d_in, const int* in_sizes, int n_in,
                              void* d_out, int out_size)
{
    const float* state = (const float*)d_in[0];
    const float* rW1   = (const float*)d_in[1];
    const float* rb1   = (const float*)d_in[2];
    const float* rW2   = (const float*)d_in[3];
    const float* rb2   = (const float*)d_in[4];
    const float* rW3   = (const float*)d_in[5];
    const float* rb3   = (const float*)d_in[6];
    const float* eW1   = (const float*)d_in[7];
    const float* eb1   = (const float*)d_in[8];
    const float* eW2   = (const float*)d_in[9];
    const float* eb2   = (const float*)d_in[10];
    const float* eW3   = (const float*)d_in[11];
    const float* eb3   = (const float*)d_in[12];
    float* out = (float*)d_out;

    k_rootlin<DD, 0, 0, true ><<<dim3(BB / 4, HH / 64), 512>>>(state, rW1, rb1);
    k_rootlin<HH, 1, 1, false><<<dim3(BB / 4, HH / 64), 512>>>(nullptr, rW2, rb2);
    k_roothead<<<BB, 512>>>(rW3, rb3);

    k_exp<DD, 4, HH,  0, 0, 4><<<dim3(EE, 4, 4), 256>>>(state,  eW1);
    k_red<HH, 0><<<(BB * HH / 4) / 256, 256>>>(eb1);
    k_exp<HH, 4, HH,  1, 1, 4><<<dim3(EE, 4, 4), 256>>>(nullptr, eW2);
    k_red<HH, 1><<<(BB * HH / 4) / 256, 256>>>(eb2);
    k_exp<HH, 8, NLF, 2, 2, 4><<<dim3(EE, 8, 4), 256>>>(nullptr, eW3);
    k_final<<<BB, 256>>>(out, eb3);
}